// round 15
// baseline (speedup 1.0000x reference)
#include <cuda_runtime.h>
#include <cuda_fp16.h>
#include <math.h>
#include <stdint.h>

#define BB     32
#define SS     577
#define HID    1408
#define H3     4224
#define NH     16
#define HD     88
#define BH     (BB*NH)      // 512
#define MROWS  (BB*SS)      // 18464
#define K2Q    (HID/2)      // 704
#define D2     48           // padded per-head d-pairs for Q
#define KST    44           // compact d-pairs for K
#define NT9    9            // full kv tiles (0..575); key 576 handled scalar
#define QSCALE (0.10660035817780521f * 1.4426950408889634f)  // 88^-.5 * log2e

// ---------------- scratch (static device globals) ----------------------------
__device__ __align__(16) __half g_xh [(size_t)MROWS * HID];   // x fp16
__device__ __align__(16) __half g_wqt[(size_t)H3 * HID];      // w_qkv^T fp16 [n][k]
__device__ __align__(16) __half g_wot[(size_t)HID * HID];     // w_o^T fp16
__device__ __align__(16) __half g_vh [(size_t)MROWS * HID];   // V compact fp16
__device__ uint32_t g_q  [(size_t)BH * SS * D2];    // Q fp16x2 P8-perm, pre-scaled
__device__ uint32_t g_k  [(size_t)BH * SS * KST];   // K fp16x2 natural pairs
__device__ __align__(16) uint32_t g_att[(size_t)MROWS * K2Q]; // att fp16 K-major

// ---------------- helpers ----------------------------------------------------
__device__ __forceinline__ uint32_t smem_u32(const void* p) {
    return (uint32_t)__cvta_generic_to_shared(p);
}
__device__ __forceinline__ void cp_async16(uint32_t dst, const void* src) {
    asm volatile("cp.async.cg.shared.global [%0], [%1], 16;\n" :: "r"(dst), "l"(src));
}
__device__ __forceinline__ void cp_commit() {
    asm volatile("cp.async.commit_group;\n");
}
__device__ __forceinline__ uint32_t packh2(float lo, float hi) {
    __half2 h = __floats2half2_rn(lo, hi);
    return *reinterpret_cast<uint32_t*>(&h);
}
__device__ __forceinline__ float2 u2f2(uint32_t u) {
    return __half22float2(*reinterpret_cast<__half2*>(&u));
}
__device__ __forceinline__ float ex2(float x) {
    float y;
    asm("ex2.approx.ftz.f32 %0, %1;" : "=f"(y) : "f"(x));
    return y;
}
__device__ __forceinline__ void mma_f16(float c[4], const uint32_t a[4], const uint32_t b[2]) {
    asm volatile(
        "mma.sync.aligned.m16n8k16.row.col.f32.f16.f16.f32 "
        "{%0,%1,%2,%3}, {%4,%5,%6,%7}, {%8,%9}, {%0,%1,%2,%3};\n"
        : "+f"(c[0]), "+f"(c[1]), "+f"(c[2]), "+f"(c[3])
        : "r"(a[0]), "r"(a[1]), "r"(a[2]), "r"(a[3]), "r"(b[0]), "r"(b[1]));
}
#define LDSM4(r0, r1, r2, r3, addr)                                             \
    asm volatile("ldmatrix.sync.aligned.m8n8.x4.shared.b16 {%0,%1,%2,%3}, [%4];" \
                 : "=r"(r0), "=r"(r1), "=r"(r2), "=r"(r3) : "r"(addr))
#define LDSM4T(r0, r1, r2, r3, addr)                                            \
    asm volatile("ldmatrix.sync.aligned.m8n8.x4.trans.shared.b16 {%0,%1,%2,%3}, [%4];" \
                 : "=r"(r0), "=r"(r1), "=r"(r2), "=r"(r3) : "r"(addr))
__device__ __forceinline__ int P8(int t) {
    return (t < 4) ? (2 * t) : (2 * (t - 4) + 1);
}

// ---------------- prep: x fp32 -> fp16 plain ---------------------------------
__global__ __launch_bounds__(256) void pack_xh(
    const float* __restrict__ x, __half* __restrict__ xh, long long n8)
{
    long long i = (long long)blockIdx.x * 256 + threadIdx.x;
    if (i >= n8) return;
    float4 a = ((const float4*)x)[2 * i];
    float4 b = ((const float4*)x)[2 * i + 1];
    uint4 o;
    o.x = packh2(a.x, a.y); o.y = packh2(a.z, a.w);
    o.z = packh2(b.x, b.y); o.w = packh2(b.z, b.w);
    ((uint4*)xh)[i] = o;
}

// ---------------- prep: w [K][N] fp32 -> wt [N][K] fp16 ----------------------
__global__ __launch_bounds__(256) void transpose_pack(
    const float* __restrict__ w, __half* __restrict__ wt, int K, int N)
{
    __shared__ float t[32][33];
    const int n0 = blockIdx.x * 32;
    const int k0 = blockIdx.y * 32;
    const int tx = threadIdx.x & 31;
    const int ty = threadIdx.x >> 5;
    for (int i = ty; i < 32; i += 8)
        t[i][tx] = w[(size_t)(k0 + i) * N + n0 + tx];
    __syncthreads();
    for (int i = ty; i < 32; i += 8)
        wt[(size_t)(n0 + i) * K + k0 + tx] = __float2half_rn(t[tx][i]);
}

// ---------------- fp16 GEMM + bias: BM=128, BN=64, 3 blocks/SM ---------------
// mode 0: C fp32 = A@B^T + bias.   mode 2: qkv -> rope-scatter Q,K + compact V.
#define ROWB   144
#define HSTAGE 27648     // A 128*144 + B 64*144

__global__ __launch_bounds__(256, 3) void h16_gemm_ldsm(
    const __half* __restrict__ A, const __half* __restrict__ Bt,
    const float* __restrict__ bias, float* __restrict__ Cf,
    uint32_t* __restrict__ Qp, uint32_t* __restrict__ Kp,
    __half* __restrict__ Vh,
    int M, int N, int K, int mode)
{
    extern __shared__ __align__(16) char gsm[];
    __shared__ float sbias[64];

    const int tid  = threadIdx.x;
    const int brow = blockIdx.y * 128;
    const int bcol = blockIdx.x * 64;
    const int wid  = tid >> 5;
    const int lane = tid & 31;
    const int g    = lane >> 2;
    const int t4   = lane & 3;
    const int wm   = (wid >> 1) * 32;   // 0/32/64/96
    const int wn   = (wid & 1) * 32;    // 0/32

    if (tid < 64) sbias[tid] = bias[bcol + tid];

    const uint32_t sb = smem_u32(gsm);
    const uint32_t a_off = (uint32_t)(wm + (lane & 15)) * ROWB + ((lane >> 4) << 4);
    const uint32_t b_off = (uint32_t)(wn + (lane & 7) + ((lane >> 4) << 3)) * ROWB
                           + (((lane >> 3) & 1) << 4);

    float acc[2][4][4];
#pragma unroll
    for (int mi = 0; mi < 2; mi++)
#pragma unroll
        for (int ni = 0; ni < 4; ni++)
#pragma unroll
            for (int r = 0; r < 4; r++) acc[mi][ni][r] = 0.f;

    const int nk = K / 64;

#define GLOADS(s, c)                                                           \
    {                                                                          \
        const uint32_t sA = sb + (s) * HSTAGE;                                 \
        const uint32_t sB = sA + 128 * ROWB;                                   \
        const int kc = (c) * 64;                                               \
        _Pragma("unroll")                                                      \
        for (int t = 0; t < 6; t++) {                                          \
            int idx = tid + 256 * t;                                           \
            if (t < 4) {                                                       \
                int row = idx >> 3, cc = idx & 7;                              \
                int ra = brow + row; if (ra >= M) ra = M - 1;                  \
                cp_async16(sA + row * ROWB + cc * 16,                          \
                           A + (size_t)ra * K + kc + cc * 8);                  \
            } else {                                                           \
                int i2 = idx - 1024;                                           \
                int row = i2 >> 3, cc = i2 & 7;                                \
                cp_async16(sB + row * ROWB + cc * 16,                          \
                           Bt + (size_t)(bcol + row) * K + kc + cc * 8);       \
            }                                                                  \
        }                                                                      \
        cp_commit();                                                           \
    }

    GLOADS(0, 0);

    for (int it = 0; it < nk; ++it) {
        const int s = it & 1;
        if (it + 1 < nk) {
            GLOADS((it + 1) & 1, it + 1);
            asm volatile("cp.async.wait_group 1;\n" ::: "memory");
        } else {
            asm volatile("cp.async.wait_group 0;\n" ::: "memory");
        }
        __syncthreads();

        const uint32_t sA = sb + s * HSTAGE;
        const uint32_t sB = sA + 128 * ROWB;
#pragma unroll
        for (int kkl = 0; kkl < 4; kkl++) {
            uint32_t af[2][4], bf[2][4];
#pragma unroll
            for (int mi = 0; mi < 2; mi++)
                LDSM4(af[mi][0], af[mi][1], af[mi][2], af[mi][3],
                      sA + a_off + mi * (16 * ROWB) + kkl * 32);
#pragma unroll
            for (int nj = 0; nj < 2; nj++)
                LDSM4(bf[nj][0], bf[nj][1], bf[nj][2], bf[nj][3],
                      sB + b_off + nj * (16 * ROWB) + kkl * 32);
#pragma unroll
            for (int mi = 0; mi < 2; mi++)
#pragma unroll
                for (int ni = 0; ni < 4; ni++) {
                    uint32_t bb[2] = {bf[ni >> 1][(ni & 1) * 2],
                                      bf[ni >> 1][(ni & 1) * 2 + 1]};
                    mma_f16(acc[mi][ni], af[mi], bb);
                }
        }
        __syncthreads();
    }

    if (mode == 0) {
#pragma unroll
        for (int mi = 0; mi < 2; mi++)
#pragma unroll
            for (int ni = 0; ni < 4; ni++) {
                int r0 = brow + wm + mi * 16 + g;
                int c0 = bcol + wn + ni * 8 + t4 * 2;
                float bx = sbias[wn + ni * 8 + t4 * 2];
                float by = sbias[wn + ni * 8 + t4 * 2 + 1];
                if (r0 < M) {
                    Cf[(size_t)r0 * N + c0]     = acc[mi][ni][0] + bx;
                    Cf[(size_t)r0 * N + c0 + 1] = acc[mi][ni][1] + by;
                }
                if (r0 + 8 < M) {
                    Cf[(size_t)(r0 + 8) * N + c0]     = acc[mi][ni][2] + bx;
                    Cf[(size_t)(r0 + 8) * N + c0 + 1] = acc[mi][ni][3] + by;
                }
            }
    } else {
        // fused rope / scatter epilogue for QKV
        const int part = bcol / HID;          // 0=Q, 1=K, 2=V
#pragma unroll
        for (int mi = 0; mi < 2; mi++) {
            const int r0 = brow + wm + mi * 16 + g;
#pragma unroll
            for (int ni = 0; ni < 4; ni++) {
                const int lc = wn + ni * 8 + t4 * 2;
                const int cw = bcol - part * HID + lc;     // col within part
                const float bx = sbias[lc];
                const float by = sbias[lc + 1];
                if (part == 2) {
                    if (r0 < M)
                        *(__half2*)(Vh + (size_t)r0 * HID + cw) =
                            __floats2half2_rn(acc[mi][ni][0] + bx, acc[mi][ni][1] + by);
                    if (r0 + 8 < M)
                        *(__half2*)(Vh + (size_t)(r0 + 8) * HID + cw) =
                            __floats2half2_rn(acc[mi][ni][2] + bx, acc[mi][ni][3] + by);
                } else {
                    const int h = cw / 88;
                    const int d = cw - 88 * h;
                    const int j = d >> 1;
                    const int jj = (j < 22) ? j : (j - 22);
                    const float inv = __expf(-(float)jj * 0.41865183508982657f);
                    const bool isQ = (part == 0);
                    const float qs = isQ ? QSCALE : 1.f;
                    const int jpos = isQ ? ((j & ~7) + P8(j & 7)) : j;
                    const int dstride = isQ ? D2 : KST;
                    uint32_t* dstbase = isQ ? Qp : Kp;
#pragma unroll
                    for (int half = 0; half < 2; half++) {
                        int r = r0 + 8 * half;
                        if (r >= M) continue;
                        int b = r / SS, s = r - b * SS;
                        float c, sn;
                        if (s == SS - 1) {
                            c = 1.f; sn = 0.f;
                        } else {
                            int fx = s % 24, fy = s / 24;
                            int coord = (j < 22) ? (fx + 1) : (fy + 1);
                            __sincosf((float)coord * inv, &sn, &c);
                        }
                        float x0 = acc[mi][ni][2 * half]     + bx;
                        float x1 = acc[mi][ni][2 * half + 1] + by;
                        float o0 = (x0 * c - x1 * sn) * qs;
                        float o1 = (x0 * sn + x1 * c) * qs;
                        dstbase[((size_t)(b * NH + h) * SS + s) * dstride + jpos] =
                            packh2(o0, o1);
                    }
                }
            }
        }
    }
#undef GLOADS
}

// ---------------- fused flash attention (fp16 mma, 9 full tiles + scalar key) -
#define FROWB   208
#define FSTAGE  (2 * 64 * FROWB)     // K + V per stage = 26624
#define FSMEM   (3 * FSTAGE)         // 79872

__global__ __launch_bounds__(256, 2) void flash_attn(
    const uint32_t* __restrict__ Q, const uint32_t* __restrict__ K,
    const __half* __restrict__ Vh, uint32_t* __restrict__ O)
{
    extern __shared__ __align__(16) char fsm[];
    const uint32_t sb = smem_u32(fsm);

    const int bh  = blockIdx.y;
    const int q0  = blockIdx.x * 128;
    const int tid = threadIdx.x;
    const int wid = tid >> 5;
    const int lane = tid & 31;
    const int g   = lane >> 2;
    const int t4  = lane & 3;

    const uint32_t* Qb = Q + (size_t)bh * SS * D2;
    const uint32_t* Kb = K + (size_t)bh * SS * KST;
    const int bb = bh >> 4, hh = bh & 15;
    const __half* Vb = Vh + (size_t)(bb * SS) * HID + hh * HD;

    const bool wact = (q0 + wid * 16) < SS;   // warp has >=1 valid q row

    // zero pad columns [176,208) of all 384 rows (once; loads never touch them)
    for (int idx = tid; idx < 768; idx += 256) {
        int r = idx >> 1, c = idx & 1;
        *(float4*)(fsm + r * FROWB + 176 + c * 16) =
            make_float4(0.f, 0.f, 0.f, 0.f);
    }

    // preload Q fragments (P8-permuted pairs, zero-padded beyond d=88)
    const int r0 = q0 + wid * 16 + g;
    const int r1 = r0 + 8;
    const int r0c = (r0 < SS) ? r0 : (SS - 1);
    const int r1c = (r1 < SS) ? r1 : (SS - 1);
    uint32_t qf[6][4];
#pragma unroll
    for (int kk = 0; kk < 6; kk++) {
        uint2 lo = *(const uint2*)(Qb + (size_t)r0c * D2 + 8 * kk + 2 * t4);
        uint2 hi = *(const uint2*)(Qb + (size_t)r1c * D2 + 8 * kk + 2 * t4);
        qf[kk][0] = lo.x; qf[kk][1] = hi.x;
        qf[kk][2] = lo.y; qf[kk][3] = hi.y;
    }

    // preload last key (kv=576) pairs and its V row (per-lane slices)
    uint32_t k576a[6], k576b[5], v576[11];
    if (wact) {
        const uint32_t* k576 = Kb + (size_t)(SS - 1) * KST;
        const uint32_t* vl   = (const uint32_t*)(Vb + (size_t)(SS - 1) * HID);
#pragma unroll
        for (int kk = 0; kk < 6; kk++) k576a[kk] = __ldg(k576 + 8 * kk + t4);
#pragma unroll
        for (int kk = 0; kk < 5; kk++) k576b[kk] = __ldg(k576 + 8 * kk + t4 + 4);
#pragma unroll
        for (int ni = 0; ni < 11; ni++) v576[ni] = __ldg(vl + ni * 4 + t4);
    }

    float oacc[11][4];
#pragma unroll
    for (int ni = 0; ni < 11; ni++)
#pragma unroll
        for (int r = 0; r < 4; r++) oacc[ni][r] = 0.f;
    float m0 = -1e30f, m1 = -1e30f, l0 = 0.f, l1 = 0.f;

    // ldmatrix lane-invariant offsets
    const uint32_t k_off = (uint32_t)((lane & 7) + ((lane >> 4) << 3)) * FROWB
                           + (((lane >> 3) & 1) << 4);
    const uint32_t vt_off = (uint32_t)((lane & 7) + (((lane >> 3) & 1) << 3)) * FROWB
                            + ((lane >> 4) << 4);

#define LOAD_TILE(s, j0v)                                                  \
    {                                                                      \
        const uint32_t sK = sb + (s) * FSTAGE;                             \
        const uint32_t sV = sK + 64 * FROWB;                               \
        for (int idx = tid; idx < 1408; idx += 256) {                      \
            int half = idx >= 704;                                         \
            int i2 = idx - half * 704;                                     \
            int row = i2 / 11, c = i2 % 11;                                \
            int jr = (j0v) + row;                                          \
            if (!half)                                                     \
                cp_async16(sK + row * FROWB + c * 16,                      \
                           Kb + (size_t)jr * KST + c * 4);                 \
            else                                                           \
                cp_async16(sV + row * FROWB + c * 16,                      \
                           Vb + (size_t)jr * HID + c * 8);                 \
        }                                                                  \
        cp_commit();                                                       \
    }

    LOAD_TILE(0, 0);
    LOAD_TILE(1, 64);

    for (int it = 0; it < NT9; ++it) {
        const int s = it % 3;
        if (it + 1 < NT9)
            asm volatile("cp.async.wait_group 1;\n" ::: "memory");
        else
            asm volatile("cp.async.wait_group 0;\n" ::: "memory");
        __syncthreads();
        if (it + 2 < NT9) LOAD_TILE((it + 2) % 3, (it + 2) * 64);

        if (!wact) continue;   // tail warps: loads+syncs only

        const uint32_t sK = sb + s * FSTAGE;
        const uint32_t sV = sK + 64 * FROWB;

        // ---- S = Q K^T : pipelined K-frag ldmatrix (p fastest) ----
        float sacc[8][4];
#pragma unroll
        for (int ni = 0; ni < 8; ni++)
#pragma unroll
            for (int r = 0; r < 4; r++) sacc[ni][r] = 0.f;

        {
            uint32_t kf[2][4];
            LDSM4(kf[0][0], kf[0][1], kf[0][2], kf[0][3], sK + k_off);
#pragma unroll
            for (int i = 0; i < 24; i++) {
                if (i + 1 < 24) {
                    const int pn = (i + 1) & 3, kn = (i + 1) >> 2;
                    LDSM4(kf[(i + 1) & 1][0], kf[(i + 1) & 1][1],
                          kf[(i + 1) & 1][2], kf[(i + 1) & 1][3],
                          sK + k_off + pn * (16 * FROWB) + kn * 32);
                }
                const int p = i & 3, kk = i >> 2;
                uint32_t b0[2] = {kf[i & 1][0], kf[i & 1][1]};
                uint32_t b1[2] = {kf[i & 1][2], kf[i & 1][3]};
                mma_f16(sacc[2 * p],     qf[kk], b0);
                mma_f16(sacc[2 * p + 1], qf[kk], b1);
            }
        }

        // ---- online softmax (base-2; Q pre-scaled). all kv cols valid ----
        float mx0 = -1e30f, mx1 = -1e30f;
#pragma unroll
        for (int ni = 0; ni < 8; ni++) {
            mx0 = fmaxf(mx0, fmaxf(sacc[ni][0], sacc[ni][1]));
            mx1 = fmaxf(mx1, fmaxf(sacc[ni][2], sacc[ni][3]));
        }
#pragma unroll
        for (int off = 1; off < 4; off <<= 1) {
            mx0 = fmaxf(mx0, __shfl_xor_sync(0xffffffffu, mx0, off));
            mx1 = fmaxf(mx1, __shfl_xor_sync(0xffffffffu, mx1, off));
        }

        float m0n = fmaxf(m0, mx0);
        float m1n = fmaxf(m1, mx1);
        float a0 = ex2(m0 - m0n);
        float a1 = ex2(m1 - m1n);

        float rs0 = 0.f, rs1 = 0.f;
#pragma unroll
        for (int ni = 0; ni < 8; ni++) {
            sacc[ni][0] = ex2(sacc[ni][0] - m0n);
            sacc[ni][1] = ex2(sacc[ni][1] - m0n);
            sacc[ni][2] = ex2(sacc[ni][2] - m1n);
            sacc[ni][3] = ex2(sacc[ni][3] - m1n);
            rs0 += sacc[ni][0] + sacc[ni][1];
            rs1 += sacc[ni][2] + sacc[ni][3];
        }
#pragma unroll
        for (int off = 1; off < 4; off <<= 1) {
            rs0 += __shfl_xor_sync(0xffffffffu, rs0, off);
            rs1 += __shfl_xor_sync(0xffffffffu, rs1, off);
        }
        l0 = l0 * a0 + rs0;
        l1 = l1 * a1 + rs1;
        m0 = m0n;
        m1 = m1n;

        if (__any_sync(0xffffffffu, (a0 < 1.f) | (a1 < 1.f))) {
#pragma unroll
            for (int ni = 0; ni < 11; ni++) {
                oacc[ni][0] *= a0;
                oacc[ni][1] *= a0;
                oacc[ni][2] *= a1;
                oacc[ni][3] *= a1;
            }
        }

        // ---- O += P V : pre-pack P frags, pipelined V-frag ldmatrix.trans ----
        {
            uint32_t af[4][4];
#pragma unroll
            for (int kk = 0; kk < 4; kk++) {
                af[kk][0] = packh2(sacc[2*kk][0],   sacc[2*kk][1]);
                af[kk][1] = packh2(sacc[2*kk][2],   sacc[2*kk][3]);
                af[kk][2] = packh2(sacc[2*kk+1][0], sacc[2*kk+1][1]);
                af[kk][3] = packh2(sacc[2*kk+1][2], sacc[2*kk+1][3]);
            }
            uint32_t vf[2][4];
            LDSM4T(vf[0][0], vf[0][1], vf[0][2], vf[0][3], sV + vt_off);
#pragma unroll
            for (int i = 0; i < 24; i++) {
                if (i + 1 < 24) {
                    const int kn = (i + 1) / 6, nn = (i + 1) % 6;
                    LDSM4T(vf[(i + 1) & 1][0], vf[(i + 1) & 1][1],
                           vf[(i + 1) & 1][2], vf[(i + 1) & 1][3],
                           sV + vt_off + kn * (16 * FROWB) + nn * 32);
                }
                const int kk = i / 6, np = i % 6;
                uint32_t b0[2] = {vf[i & 1][0], vf[i & 1][1]};
                mma_f16(oacc[2 * np], af[kk], b0);
                if (np < 5) {
                    uint32_t b1[2] = {vf[i & 1][2], vf[i & 1][3]};
                    mma_f16(oacc[2 * np + 1], af[kk], b1);
                }
            }
        }
        // 3-stage ring: stage s is rewritten only after the next barrier.
    }

    if (wact) {
        // ---- scalar step for the last key (kv = 576) ----
        float e0 = 0.f, e1 = 0.f;
#pragma unroll
        for (int kk = 0; kk < 6; kk++) {
            float2 kp = u2f2(k576a[kk]);
            float2 qa = u2f2(qf[kk][0]);
            float2 qb = u2f2(qf[kk][1]);
            e0 += qa.x * kp.x + qa.y * kp.y;
            e1 += qb.x * kp.x + qb.y * kp.y;
            if (kk < 5) {
                float2 kq = u2f2(k576b[kk]);
                float2 qc = u2f2(qf[kk][2]);
                float2 qd = u2f2(qf[kk][3]);
                e0 += qc.x * kq.x + qc.y * kq.y;
                e1 += qd.x * kq.x + qd.y * kq.y;
            }
        }
#pragma unroll
        for (int off = 1; off < 4; off <<= 1) {
            e0 += __shfl_xor_sync(0xffffffffu, e0, off);
            e1 += __shfl_xor_sync(0xffffffffu, e1, off);
        }
        float m0n = fmaxf(m0, e0);
        float m1n = fmaxf(m1, e1);
        float a0 = ex2(m0 - m0n);
        float a1 = ex2(m1 - m1n);
        float p0 = ex2(e0 - m0n);
        float p1 = ex2(e1 - m1n);
        l0 = l0 * a0 + p0;
        l1 = l1 * a1 + p1;
#pragma unroll
        for (int ni = 0; ni < 11; ni++) {
            float2 v = u2f2(v576[ni]);
            oacc[ni][0] = oacc[ni][0] * a0 + p0 * v.x;
            oacc[ni][1] = oacc[ni][1] * a0 + p0 * v.y;
            oacc[ni][2] = oacc[ni][2] * a1 + p1 * v.x;
            oacc[ni][3] = oacc[ni][3] * a1 + p1 * v.y;
        }
    }

    // ---- normalize + store plain K-major fp16 pairs (gemm A layout) ----
    const float il0 = 1.f / l0;
    const float il1 = 1.f / l1;
    if (r0 < SS) {
        uint32_t* o = O + (size_t)(bb * SS + r0) * K2Q;
#pragma unroll
        for (int ni = 0; ni < 11; ni++)
            o[hh * 44 + ni * 4 + t4] = packh2(oacc[ni][0] * il0, oacc[ni][1] * il0);
    }
    if (r1 < SS) {
        uint32_t* o = O + (size_t)(bb * SS + r1) * K2Q;
#pragma unroll
        for (int ni = 0; ni < 11; ni++)
            o[hh * 44 + ni * 4 + t4] = packh2(oacc[ni][2] * il1, oacc[ni][3] * il1);
    }
#undef LOAD_TILE
}

// ---------------- launch -----------------------------------------------------
extern "C" void kernel_launch(void* const* d_in, const int* in_sizes, int n_in,
                              void* d_out, int out_size)
{
    const float* x     = (const float*)d_in[0];
    const float* w_qkv = (const float*)d_in[1];
    const float* b_qkv = (const float*)d_in[2];
    const float* w_o   = (const float*)d_in[3];
    const float* b_o   = (const float*)d_in[4];
    float* out = (float*)d_out;

    __half *xh, *wqt, *wot, *vh;
    uint32_t *q, *k, *att;
    cudaGetSymbolAddress((void**)&xh,  g_xh);
    cudaGetSymbolAddress((void**)&wqt, g_wqt);
    cudaGetSymbolAddress((void**)&wot, g_wot);
    cudaGetSymbolAddress((void**)&vh,  g_vh);
    cudaGetSymbolAddress((void**)&q,   g_q);
    cudaGetSymbolAddress((void**)&k,   g_k);
    cudaGetSymbolAddress((void**)&att, g_att);

    const int gemm_smem = 2 * HSTAGE;   // 55296
    cudaFuncSetAttribute(h16_gemm_ldsm,
                         cudaFuncAttributeMaxDynamicSharedMemorySize, gemm_smem);

    // 0) prep: x -> fp16; weights -> transposed fp16
    {
        long long n8 = (long long)MROWS * HID / 8;
        pack_xh<<<(int)((n8 + 255) / 256), 256>>>(x, xh, n8);
        transpose_pack<<<dim3(H3 / 32, HID / 32), 256>>>(w_qkv, wqt, HID, H3);
        transpose_pack<<<dim3(HID / 32, HID / 32), 256>>>(w_o, wot, HID, HID);
    }

    // 1) QKV projection with fused rope/scatter epilogue (BN=64 tiles)
    h16_gemm_ldsm<<<dim3(H3 / 64, (MROWS + 127) / 128), 256, gemm_smem>>>(
        xh, wqt, b_qkv, nullptr, q, k, vh, MROWS, H3, HID, 2);

    // 2) fused flash attention (V read directly from vh) -> att
    {
        cudaFuncSetAttribute(flash_attn,
                             cudaFuncAttributeMaxDynamicSharedMemorySize,
                             FSMEM);
        flash_attn<<<dim3((SS + 127) / 128, BH), 256, FSMEM>>>(q, k, vh, att);
    }

    // 3) output projection -> fp32 out
    h16_gemm_ldsm<<<dim3(HID / 64, (MROWS + 127) / 128), 256, gemm_smem>>>(
        (const __half*)att, wot, b_o, out, nullptr, nullptr, nullptr,
        MROWS, HID, HID, 0);
}

// round 16
// speedup vs baseline: 1.0821x; 1.0821x over previous
#include <cuda_runtime.h>
#include <cuda_fp16.h>
#include <math.h>
#include <stdint.h>

#define BB     32
#define SS     577
#define HID    1408
#define H3     4224
#define NH     16
#define HD     88
#define BH     (BB*NH)      // 512
#define MROWS  (BB*SS)      // 18464
#define K2Q    (HID/2)      // 704
#define D2     48           // padded per-head d-pairs for Q
#define KST    44           // compact d-pairs for K
#define NT     10
#define QSCALE (0.10660035817780521f * 1.4426950408889634f)  // 88^-.5 * log2e

// fused prep grid split
#define PREP_N8    ((long long)MROWS * HID / 8)       // 3249664
#define PREP_B1    12694                              // ceil(PREP_N8/256)
#define PREP_B2    (PREP_B1 + (H3/32) * (HID/32))     // + 5808
#define PREP_B3    (PREP_B2 + (HID/32) * (HID/32))    // + 1936

// ---------------- scratch (static device globals) ----------------------------
__device__ __align__(16) __half g_xh [(size_t)MROWS * HID];   // x fp16
__device__ __align__(16) __half g_wqt[(size_t)H3 * HID];      // w_qkv^T fp16 [n][k]
__device__ __align__(16) __half g_wot[(size_t)HID * HID];     // w_o^T fp16
__device__ __align__(16) __half g_vh [(size_t)MROWS * HID];   // V compact fp16
__device__ uint32_t g_q  [(size_t)BH * SS * D2];    // Q fp16x2 P8-perm, pre-scaled
__device__ uint32_t g_k  [(size_t)BH * SS * KST];   // K fp16x2 natural pairs
__device__ __align__(16) uint32_t g_att[(size_t)MROWS * K2Q]; // att fp16 K-major

// ---------------- helpers ----------------------------------------------------
__device__ __forceinline__ uint32_t smem_u32(const void* p) {
    return (uint32_t)__cvta_generic_to_shared(p);
}
__device__ __forceinline__ void cp_async16(uint32_t dst, const void* src) {
    asm volatile("cp.async.cg.shared.global [%0], [%1], 16;\n" :: "r"(dst), "l"(src));
}
__device__ __forceinline__ void cp_commit() {
    asm volatile("cp.async.commit_group;\n");
}
__device__ __forceinline__ uint32_t packh2(float lo, float hi) {
    __half2 h = __floats2half2_rn(lo, hi);
    return *reinterpret_cast<uint32_t*>(&h);
}
__device__ __forceinline__ float ex2(float x) {
    float y;
    asm("ex2.approx.ftz.f32 %0, %1;" : "=f"(y) : "f"(x));
    return y;
}
__device__ __forceinline__ void mma_f16(float c[4], const uint32_t a[4], const uint32_t b[2]) {
    asm volatile(
        "mma.sync.aligned.m16n8k16.row.col.f32.f16.f16.f32 "
        "{%0,%1,%2,%3}, {%4,%5,%6,%7}, {%8,%9}, {%0,%1,%2,%3};\n"
        : "+f"(c[0]), "+f"(c[1]), "+f"(c[2]), "+f"(c[3])
        : "r"(a[0]), "r"(a[1]), "r"(a[2]), "r"(a[3]), "r"(b[0]), "r"(b[1]));
}
#define LDSM4(r0, r1, r2, r3, addr)                                             \
    asm volatile("ldmatrix.sync.aligned.m8n8.x4.shared.b16 {%0,%1,%2,%3}, [%4];" \
                 : "=r"(r0), "=r"(r1), "=r"(r2), "=r"(r3) : "r"(addr))
#define LDSM4T(r0, r1, r2, r3, addr)                                            \
    asm volatile("ldmatrix.sync.aligned.m8n8.x4.trans.shared.b16 {%0,%1,%2,%3}, [%4];" \
                 : "=r"(r0), "=r"(r1), "=r"(r2), "=r"(r3) : "r"(addr))
__device__ __forceinline__ int P8(int t) {
    return (t < 4) ? (2 * t) : (2 * (t - 4) + 1);
}

// ---------------- fused prep: pack x + transpose both weights ----------------
__global__ __launch_bounds__(256) void prep_all(
    const float* __restrict__ x, __half* __restrict__ xh,
    const float* __restrict__ wq, __half* __restrict__ wqt,
    const float* __restrict__ wo, __half* __restrict__ wot)
{
    __shared__ float t[32][33];
    const int bid = blockIdx.x;
    const int tid = threadIdx.x;

    if (bid < PREP_B1) {
        long long i = (long long)bid * 256 + tid;
        if (i < PREP_N8) {
            float4 a = ((const float4*)x)[2 * i];
            float4 b = ((const float4*)x)[2 * i + 1];
            uint4 o;
            o.x = packh2(a.x, a.y); o.y = packh2(a.z, a.w);
            o.z = packh2(b.x, b.y); o.w = packh2(b.z, b.w);
            ((uint4*)xh)[i] = o;
        }
        return;
    }

    const float* w; __half* wt; int K, N, n0, k0;
    if (bid < PREP_B2) {
        int b2 = bid - PREP_B1;
        w = wq; wt = wqt; K = HID; N = H3;
        n0 = (b2 % (H3 / 32)) * 32;
        k0 = (b2 / (H3 / 32)) * 32;
    } else {
        int b3 = bid - PREP_B2;
        w = wo; wt = wot; K = HID; N = HID;
        n0 = (b3 % (HID / 32)) * 32;
        k0 = (b3 / (HID / 32)) * 32;
    }
    const int tx = tid & 31;
    const int ty = tid >> 5;
    for (int i = ty; i < 32; i += 8)
        t[i][tx] = w[(size_t)(k0 + i) * N + n0 + tx];
    __syncthreads();
    for (int i = ty; i < 32; i += 8)
        wt[(size_t)(n0 + i) * K + k0 + tx] = __float2half_rn(t[tx][i]);
}

// ---------------- fp16 GEMM + bias, ldmatrix, fused rope epilogue ------------
// mode 0: C fp32 = A@B^T + bias.   mode 2: qkv -> rope-scatter Q,K + compact V.
#define ROWB   144
#define HSTAGE 36864     // A 128*144 + B 128*144

__global__ __launch_bounds__(256, 2) void h16_gemm_ldsm(
    const __half* __restrict__ A, const __half* __restrict__ Bt,
    const float* __restrict__ bias, float* __restrict__ Cf,
    uint32_t* __restrict__ Qp, uint32_t* __restrict__ Kp,
    __half* __restrict__ Vh,
    int M, int N, int K, int mode)
{
    extern __shared__ __align__(16) char gsm[];
    __shared__ float sbias[128];

    const int tid  = threadIdx.x;
    const int brow = blockIdx.y * 128;
    const int bcol = blockIdx.x * 128;
    const int wid  = tid >> 5;
    const int lane = tid & 31;
    const int g    = lane >> 2;
    const int t4   = lane & 3;
    const int wm   = (wid >> 2) * 64;
    const int wn   = (wid & 3) * 32;

    if (tid < 128) sbias[tid] = bias[bcol + tid];

    const uint32_t sb = smem_u32(gsm);
    const uint32_t a_off = (uint32_t)(wm + (lane & 15)) * ROWB + ((lane >> 4) << 4);
    const uint32_t b_off = (uint32_t)(wn + (lane & 7) + ((lane >> 4) << 3)) * ROWB
                           + (((lane >> 3) & 1) << 4);

    float acc[4][4][4];
#pragma unroll
    for (int mi = 0; mi < 4; mi++)
#pragma unroll
        for (int ni = 0; ni < 4; ni++)
#pragma unroll
            for (int r = 0; r < 4; r++) acc[mi][ni][r] = 0.f;

    const int nk = K / 64;

#define GLOADS(s, c)                                                           \
    {                                                                          \
        const uint32_t sA = sb + (s) * HSTAGE;                                 \
        const uint32_t sB = sA + 128 * ROWB;                                   \
        const int kc = (c) * 64;                                               \
        _Pragma("unroll")                                                      \
        for (int t = 0; t < 4; t++) {                                          \
            int idx = tid + 256 * t;                                           \
            int row = idx >> 3, cc = idx & 7;                                  \
            int ra = brow + row; if (ra >= M) ra = M - 1;                      \
            cp_async16(sA + row * ROWB + cc * 16,                              \
                       A + (size_t)ra * K + kc + cc * 8);                      \
            cp_async16(sB + row * ROWB + cc * 16,                              \
                       Bt + (size_t)(bcol + row) * K + kc + cc * 8);           \
        }                                                                      \
        cp_commit();                                                           \
    }

    GLOADS(0, 0);

    for (int it = 0; it < nk; ++it) {
        const int s = it & 1;
        if (it + 1 < nk) {
            GLOADS((it + 1) & 1, it + 1);
            asm volatile("cp.async.wait_group 1;\n" ::: "memory");
        } else {
            asm volatile("cp.async.wait_group 0;\n" ::: "memory");
        }
        __syncthreads();

        const uint32_t sA = sb + s * HSTAGE;
        const uint32_t sB = sA + 128 * ROWB;
#pragma unroll
        for (int kkl = 0; kkl < 4; kkl++) {
            uint32_t af[4][4], bf[2][4];
#pragma unroll
            for (int mi = 0; mi < 4; mi++)
                LDSM4(af[mi][0], af[mi][1], af[mi][2], af[mi][3],
                      sA + a_off + mi * (16 * ROWB) + kkl * 32);
#pragma unroll
            for (int nj = 0; nj < 2; nj++)
                LDSM4(bf[nj][0], bf[nj][1], bf[nj][2], bf[nj][3],
                      sB + b_off + nj * (16 * ROWB) + kkl * 32);
#pragma unroll
            for (int mi = 0; mi < 4; mi++)
#pragma unroll
                for (int ni = 0; ni < 4; ni++) {
                    uint32_t bb[2] = {bf[ni >> 1][(ni & 1) * 2],
                                      bf[ni >> 1][(ni & 1) * 2 + 1]};
                    mma_f16(acc[mi][ni], af[mi], bb);
                }
        }
        __syncthreads();
    }

    if (mode == 0) {
#pragma unroll
        for (int mi = 0; mi < 4; mi++)
#pragma unroll
            for (int ni = 0; ni < 4; ni++) {
                int r0 = brow + wm + mi * 16 + g;
                int c0 = bcol + wn + ni * 8 + t4 * 2;
                float bx = sbias[wn + ni * 8 + t4 * 2];
                float by = sbias[wn + ni * 8 + t4 * 2 + 1];
                if (r0 < M) {
                    Cf[(size_t)r0 * N + c0]     = acc[mi][ni][0] + bx;
                    Cf[(size_t)r0 * N + c0 + 1] = acc[mi][ni][1] + by;
                }
                if (r0 + 8 < M) {
                    Cf[(size_t)(r0 + 8) * N + c0]     = acc[mi][ni][2] + bx;
                    Cf[(size_t)(r0 + 8) * N + c0 + 1] = acc[mi][ni][3] + by;
                }
            }
    } else {
        // fused rope / scatter epilogue for QKV
        const int part = bcol / HID;          // 0=Q, 1=K, 2=V
#pragma unroll
        for (int mi = 0; mi < 4; mi++) {
            const int r0 = brow + wm + mi * 16 + g;
#pragma unroll
            for (int ni = 0; ni < 4; ni++) {
                const int lc = wn + ni * 8 + t4 * 2;
                const int cw = bcol - part * HID + lc;     // col within part
                const float bx = sbias[lc];
                const float by = sbias[lc + 1];
                if (part == 2) {
                    if (r0 < M)
                        *(__half2*)(Vh + (size_t)r0 * HID + cw) =
                            __floats2half2_rn(acc[mi][ni][0] + bx, acc[mi][ni][1] + by);
                    if (r0 + 8 < M)
                        *(__half2*)(Vh + (size_t)(r0 + 8) * HID + cw) =
                            __floats2half2_rn(acc[mi][ni][2] + bx, acc[mi][ni][3] + by);
                } else {
                    const int h = cw / 88;
                    const int d = cw - 88 * h;
                    const int j = d >> 1;
                    const int jj = (j < 22) ? j : (j - 22);
                    const float inv = __expf(-(float)jj * 0.41865183508982657f);
                    const bool isQ = (part == 0);
                    const float qs = isQ ? QSCALE : 1.f;
                    const int jpos = isQ ? ((j & ~7) + P8(j & 7)) : j;
                    const int dstride = isQ ? D2 : KST;
                    uint32_t* dstbase = isQ ? Qp : Kp;
#pragma unroll
                    for (int half = 0; half < 2; half++) {
                        int r = r0 + 8 * half;
                        if (r >= M) continue;
                        int b = r / SS, s = r - b * SS;
                        float c, sn;
                        if (s == SS - 1) {
                            c = 1.f; sn = 0.f;
                        } else {
                            int fx = s % 24, fy = s / 24;
                            int coord = (j < 22) ? (fx + 1) : (fy + 1);
                            __sincosf((float)coord * inv, &sn, &c);
                        }
                        float x0 = acc[mi][ni][2 * half]     + bx;
                        float x1 = acc[mi][ni][2 * half + 1] + by;
                        float o0 = (x0 * c - x1 * sn) * qs;
                        float o1 = (x0 * sn + x1 * c) * qs;
                        dstbase[((size_t)(b * NH + h) * SS + s) * dstride + jpos] =
                            packh2(o0, o1);
                    }
                }
            }
        }
    }
#undef GLOADS
}

// ---------------- fused flash attention (fp16 mma, pipelined ldmatrix) -------
#define FROWB   208
#define FSTAGE  (2 * 64 * FROWB)     // K + V per stage = 26624
#define FSMEM   (3 * FSTAGE)         // 79872

__global__ __launch_bounds__(256, 2) void flash_attn(
    const uint32_t* __restrict__ Q, const uint32_t* __restrict__ K,
    const __half* __restrict__ Vh, uint32_t* __restrict__ O)
{
    extern __shared__ __align__(16) char fsm[];
    const uint32_t sb = smem_u32(fsm);

    const int bh  = blockIdx.y;
    const int q0  = blockIdx.x * 128;
    const int tid = threadIdx.x;
    const int wid = tid >> 5;
    const int lane = tid & 31;
    const int g   = lane >> 2;
    const int t4  = lane & 3;

    const uint32_t* Qb = Q + (size_t)bh * SS * D2;
    const uint32_t* Kb = K + (size_t)bh * SS * KST;
    const int bb = bh >> 4, hh = bh & 15;
    const __half* Vb = Vh + (size_t)(bb * SS) * HID + hh * HD;

    // zero pad columns [176,208) of all 384 rows (once; loads never touch them)
    for (int idx = tid; idx < 768; idx += 256) {
        int r = idx >> 1, c = idx & 1;
        *(float4*)(fsm + r * FROWB + 176 + c * 16) =
            make_float4(0.f, 0.f, 0.f, 0.f);
    }

    // preload Q fragments (P8-permuted pairs, zero-padded beyond d=88)
    const int r0 = q0 + wid * 16 + g;
    const int r1 = r0 + 8;
    const int r0c = (r0 < SS) ? r0 : (SS - 1);
    const int r1c = (r1 < SS) ? r1 : (SS - 1);
    uint32_t qf[6][4];
#pragma unroll
    for (int kk = 0; kk < 6; kk++) {
        uint2 lo = *(const uint2*)(Qb + (size_t)r0c * D2 + 8 * kk + 2 * t4);
        uint2 hi = *(const uint2*)(Qb + (size_t)r1c * D2 + 8 * kk + 2 * t4);
        qf[kk][0] = lo.x; qf[kk][1] = hi.x;
        qf[kk][2] = lo.y; qf[kk][3] = hi.y;
    }

    float oacc[11][4];
#pragma unroll
    for (int ni = 0; ni < 11; ni++)
#pragma unroll
        for (int r = 0; r < 4; r++) oacc[ni][r] = 0.f;
    float m0 = -1e30f, m1 = -1e30f, l0 = 0.f, l1 = 0.f;

    // ldmatrix lane-invariant offsets
    const uint32_t k_off = (uint32_t)((lane & 7) + ((lane >> 4) << 3)) * FROWB
                           + (((lane >> 3) & 1) << 4);
    const uint32_t vt_off = (uint32_t)((lane & 7) + (((lane >> 3) & 1) << 3)) * FROWB
                            + ((lane >> 4) << 4);

#define LOAD_TILE(s, j0v)                                                  \
    {                                                                      \
        const uint32_t sK = sb + (s) * FSTAGE;                             \
        const uint32_t sV = sK + 64 * FROWB;                               \
        for (int idx = tid; idx < 1408; idx += 256) {                      \
            int half = idx >= 704;                                         \
            int i2 = idx - half * 704;                                     \
            int row = i2 / 11, c = i2 % 11;                                \
            int jr = (j0v) + row; jr = (jr < SS) ? jr : (SS - 1);          \
            if (!half)                                                     \
                cp_async16(sK + row * FROWB + c * 16,                      \
                           Kb + (size_t)jr * KST + c * 4);                 \
            else                                                           \
                cp_async16(sV + row * FROWB + c * 16,                      \
                           Vb + (size_t)jr * HID + c * 8);                 \
        }                                                                  \
        cp_commit();                                                       \
    }

    LOAD_TILE(0, 0);
    LOAD_TILE(1, 64);

    for (int it = 0; it < NT; ++it) {
        const int s = it % 3;
        const int j0 = it * 64;
        if (it + 1 < NT)
            asm volatile("cp.async.wait_group 1;\n" ::: "memory");
        else
            asm volatile("cp.async.wait_group 0;\n" ::: "memory");
        __syncthreads();
        if (it + 2 < NT) LOAD_TILE((it + 2) % 3, (it + 2) * 64);

        const uint32_t sK = sb + s * FSTAGE;
        const uint32_t sV = sK + 64 * FROWB;

        // ---- S = Q K^T : pipelined K-frag ldmatrix (p fastest) ----
        float sacc[8][4];
#pragma unroll
        for (int ni = 0; ni < 8; ni++)
#pragma unroll
            for (int r = 0; r < 4; r++) sacc[ni][r] = 0.f;

        {
            uint32_t kf[2][4];
            LDSM4(kf[0][0], kf[0][1], kf[0][2], kf[0][3], sK + k_off);
#pragma unroll
            for (int i = 0; i < 24; i++) {
                if (i + 1 < 24) {
                    const int pn = (i + 1) & 3, kn = (i + 1) >> 2;
                    LDSM4(kf[(i + 1) & 1][0], kf[(i + 1) & 1][1],
                          kf[(i + 1) & 1][2], kf[(i + 1) & 1][3],
                          sK + k_off + pn * (16 * FROWB) + kn * 32);
                }
                const int p = i & 3, kk = i >> 2;
                uint32_t b0[2] = {kf[i & 1][0], kf[i & 1][1]};
                uint32_t b1[2] = {kf[i & 1][2], kf[i & 1][3]};
                mma_f16(sacc[2 * p],     qf[kk], b0);
                mma_f16(sacc[2 * p + 1], qf[kk], b1);
            }
        }

        if (j0 + 64 > SS) {
#pragma unroll
            for (int ni = 0; ni < 8; ni++) {
                int c = j0 + ni * 8 + 2 * t4;
                if (c     >= SS) { sacc[ni][0] = -1e30f; sacc[ni][2] = -1e30f; }
                if (c + 1 >= SS) { sacc[ni][1] = -1e30f; sacc[ni][3] = -1e30f; }
            }
        }

        // ---- online softmax (base-2; Q pre-scaled) ----
        float mx0 = -1e30f, mx1 = -1e30f;
#pragma unroll
        for (int ni = 0; ni < 8; ni++) {
            mx0 = fmaxf(mx0, fmaxf(sacc[ni][0], sacc[ni][1]));
            mx1 = fmaxf(mx1, fmaxf(sacc[ni][2], sacc[ni][3]));
        }
#pragma unroll
        for (int off = 1; off < 4; off <<= 1) {
            mx0 = fmaxf(mx0, __shfl_xor_sync(0xffffffffu, mx0, off));
            mx1 = fmaxf(mx1, __shfl_xor_sync(0xffffffffu, mx1, off));
        }

        float m0n = fmaxf(m0, mx0);
        float m1n = fmaxf(m1, mx1);
        float a0 = ex2(m0 - m0n);
        float a1 = ex2(m1 - m1n);

        float rs0 = 0.f, rs1 = 0.f;
#pragma unroll
        for (int ni = 0; ni < 8; ni++) {
            sacc[ni][0] = ex2(sacc[ni][0] - m0n);
            sacc[ni][1] = ex2(sacc[ni][1] - m0n);
            sacc[ni][2] = ex2(sacc[ni][2] - m1n);
            sacc[ni][3] = ex2(sacc[ni][3] - m1n);
            rs0 += sacc[ni][0] + sacc[ni][1];
            rs1 += sacc[ni][2] + sacc[ni][3];
        }
#pragma unroll
        for (int off = 1; off < 4; off <<= 1) {
            rs0 += __shfl_xor_sync(0xffffffffu, rs0, off);
            rs1 += __shfl_xor_sync(0xffffffffu, rs1, off);
        }
        l0 = l0 * a0 + rs0;
        l1 = l1 * a1 + rs1;
        m0 = m0n;
        m1 = m1n;

        if (__any_sync(0xffffffffu, (a0 < 1.f) | (a1 < 1.f))) {
#pragma unroll
            for (int ni = 0; ni < 11; ni++) {
                oacc[ni][0] *= a0;
                oacc[ni][1] *= a0;
                oacc[ni][2] *= a1;
                oacc[ni][3] *= a1;
            }
        }

        // ---- O += P V : pre-pack P frags, pipelined V-frag ldmatrix.trans ----
        {
            uint32_t af[4][4];
#pragma unroll
            for (int kk = 0; kk < 4; kk++) {
                af[kk][0] = packh2(sacc[2*kk][0],   sacc[2*kk][1]);
                af[kk][1] = packh2(sacc[2*kk][2],   sacc[2*kk][3]);
                af[kk][2] = packh2(sacc[2*kk+1][0], sacc[2*kk+1][1]);
                af[kk][3] = packh2(sacc[2*kk+1][2], sacc[2*kk+1][3]);
            }
            uint32_t vf[2][4];
            LDSM4T(vf[0][0], vf[0][1], vf[0][2], vf[0][3], sV + vt_off);
#pragma unroll
            for (int i = 0; i < 24; i++) {
                if (i + 1 < 24) {
                    const int kn = (i + 1) / 6, nn = (i + 1) % 6;
                    LDSM4T(vf[(i + 1) & 1][0], vf[(i + 1) & 1][1],
                           vf[(i + 1) & 1][2], vf[(i + 1) & 1][3],
                           sV + vt_off + kn * (16 * FROWB) + nn * 32);
                }
                const int kk = i / 6, np = i % 6;
                uint32_t b0[2] = {vf[i & 1][0], vf[i & 1][1]};
                mma_f16(oacc[2 * np], af[kk], b0);
                if (np < 5) {
                    uint32_t b1[2] = {vf[i & 1][2], vf[i & 1][3]};
                    mma_f16(oacc[2 * np + 1], af[kk], b1);
                }
            }
        }
        // 3-stage ring: stage s is rewritten only after the next barrier.
    }

    // ---- normalize + store plain K-major fp16 pairs (gemm A layout) ----
    const float il0 = 1.f / l0;
    const float il1 = 1.f / l1;
    if (r0 < SS) {
        uint32_t* o = O + (size_t)(bb * SS + r0) * K2Q;
#pragma unroll
        for (int ni = 0; ni < 11; ni++)
            o[hh * 44 + ni * 4 + t4] = packh2(oacc[ni][0] * il0, oacc[ni][1] * il0);
    }
    if (r1 < SS) {
        uint32_t* o = O + (size_t)(bb * SS + r1) * K2Q;
#pragma unroll
        for (int ni = 0; ni < 11; ni++)
            o[hh * 44 + ni * 4 + t4] = packh2(oacc[ni][2] * il1, oacc[ni][3] * il1);
    }
#undef LOAD_TILE
}

// ---------------- launch -----------------------------------------------------
extern "C" void kernel_launch(void* const* d_in, const int* in_sizes, int n_in,
                              void* d_out, int out_size)
{
    const float* x     = (const float*)d_in[0];
    const float* w_qkv = (const float*)d_in[1];
    const float* b_qkv = (const float*)d_in[2];
    const float* w_o   = (const float*)d_in[3];
    const float* b_o   = (const float*)d_in[4];
    float* out = (float*)d_out;

    __half *xh, *wqt, *wot, *vh;
    uint32_t *q, *k, *att;
    cudaGetSymbolAddress((void**)&xh,  g_xh);
    cudaGetSymbolAddress((void**)&wqt, g_wqt);
    cudaGetSymbolAddress((void**)&wot, g_wot);
    cudaGetSymbolAddress((void**)&vh,  g_vh);
    cudaGetSymbolAddress((void**)&q,   g_q);
    cudaGetSymbolAddress((void**)&k,   g_k);
    cudaGetSymbolAddress((void**)&att, g_att);

    const int gemm_smem = 2 * HSTAGE;   // 73728
    cudaFuncSetAttribute(h16_gemm_ldsm,
                         cudaFuncAttributeMaxDynamicSharedMemorySize, gemm_smem);

    // 0) fused prep: x -> fp16 AND both weight transposes in one launch
    prep_all<<<PREP_B3, 256>>>(x, xh, w_qkv, wqt, w_o, wot);

    // 1) QKV projection with fused rope/scatter epilogue
    h16_gemm_ldsm<<<dim3(H3 / 128, (MROWS + 127) / 128), 256, gemm_smem>>>(
        xh, wqt, b_qkv, nullptr, q, k, vh, MROWS, H3, HID, 2);

    // 2) fused flash attention (V read directly from vh) -> att
    {
        cudaFuncSetAttribute(flash_attn,
                             cudaFuncAttributeMaxDynamicSharedMemorySize,
                             FSMEM);
        flash_attn<<<dim3((SS + 127) / 128, BH), 256, FSMEM>>>(q, k, vh, att);
    }

    // 3) output projection -> fp32 out
    h16_gemm_ldsm<<<dim3(HID / 128, (MROWS + 127) / 128), 256, gemm_smem>>>(
        (const __half*)att, wot, b_o, out, nullptr, nullptr, nullptr,
        MROWS, HID, HID, 0);
}